// round 1
// baseline (speedup 1.0000x reference)
#include <cuda_runtime.h>
#include <cuda_bf16.h>
#include <cstdint>
#include <cstdio>

// ---------------- problem constants ----------------
#define T_TOK 1024          // 2*512 tokens
#define HDIM  1024
#define IDIM  1024
#define NEXP  16
#define TOPK  4
#define LIMIT 7.0f
#define ALPHA 1.702f
#define EPS   1e-5f

// ---------------- scratch (device globals; no allocs allowed) ----------------
__device__ __nv_bfloat16 g_xn[(size_t)T_TOK * HDIM];                  // 2 MB
__device__ __nv_bfloat16 g_s[(size_t)NEXP * T_TOK * IDIM];            // 32 MB
__device__ float         g_y[(size_t)NEXP * T_TOK * HDIM];            // 64 MB
__device__ int           g_tok[NEXP * T_TOK];
__device__ float         g_gate[NEXP * T_TOK];
__device__ int           g_slot_of[T_TOK * TOPK];
__device__ int           g_cnt[NEXP];

// ---------------- small helpers ----------------
__device__ __forceinline__ uint32_t smem_u32(const void* p) {
    return (uint32_t)__cvta_generic_to_shared(p);
}
__device__ __forceinline__ void ldsm_x4(uint32_t& r0, uint32_t& r1, uint32_t& r2, uint32_t& r3, uint32_t a) {
    asm volatile("ldmatrix.sync.aligned.m8n8.x4.shared.b16 {%0,%1,%2,%3},[%4];\n"
                 : "=r"(r0), "=r"(r1), "=r"(r2), "=r"(r3) : "r"(a));
}
__device__ __forceinline__ void ldsm_x2_t(uint32_t& r0, uint32_t& r1, uint32_t a) {
    asm volatile("ldmatrix.sync.aligned.m8n8.x2.trans.shared.b16 {%0,%1},[%2];\n"
                 : "=r"(r0), "=r"(r1) : "r"(a));
}
__device__ __forceinline__ void mma_bf16(float c[4],
                                         uint32_t a0, uint32_t a1, uint32_t a2, uint32_t a3,
                                         uint32_t b0, uint32_t b1) {
    asm volatile("mma.sync.aligned.m16n8k16.row.col.f32.bf16.bf16.f32 "
                 "{%0,%1,%2,%3},{%4,%5,%6,%7},{%8,%9},{%0,%1,%2,%3};\n"
                 : "+f"(c[0]), "+f"(c[1]), "+f"(c[2]), "+f"(c[3])
                 : "r"(a0), "r"(a1), "r"(a2), "r"(a3), "r"(b0), "r"(b1));
}
__device__ __forceinline__ float swiglu(float hg, float hl) {
    float a  = fminf(hg, LIMIT);
    float bb = fminf(fmaxf(hl, -LIMIT), LIMIT);
    return a * (1.0f / (1.0f + expf(-ALPHA * a))) * (bb + 1.0f);
}

// ---------------- kernel 0: zero counters ----------------
__global__ void zero_cnt_kernel() {
    if (threadIdx.x < NEXP) g_cnt[threadIdx.x] = 0;
}

// ---------------- kernel 1: RMSNorm + fp32 router + top-4 + scatter ----------------
__global__ void __launch_bounds__(256) rms_router_kernel(
    const float* __restrict__ x, const float* __restrict__ nscale,
    const float* __restrict__ wg, const float* __restrict__ bg) {
    int t   = blockIdx.x;
    int tid = threadIdx.x;
    __shared__ float xs[HDIM];
    __shared__ float red[256];
    __shared__ float l16[NEXP];

    // load row (float4 per thread), sum of squares
    float4 v = ((const float4*)(x + (size_t)t * HDIM))[tid];
    float ss = v.x * v.x + v.y * v.y + v.z * v.z + v.w * v.w;
    #pragma unroll
    for (int o = 16; o; o >>= 1) ss += __shfl_xor_sync(0xFFFFFFFFu, ss, o);
    if ((tid & 31) == 0) red[tid >> 5] = ss;
    __syncthreads();
    if (tid == 0) {
        float s = 0.f;
        #pragma unroll
        for (int i = 0; i < 8; i++) s += red[i];
        red[0] = rsqrtf(s * (1.0f / HDIM) + EPS);
    }
    __syncthreads();
    float r = red[0];
    float4 sc = ((const float4*)nscale)[tid];
    float4 xn4 = make_float4(v.x * r * sc.x, v.y * r * sc.y, v.z * r * sc.z, v.w * r * sc.w);
    xs[tid * 4 + 0] = xn4.x; xs[tid * 4 + 1] = xn4.y;
    xs[tid * 4 + 2] = xn4.z; xs[tid * 4 + 3] = xn4.w;
    __nv_bfloat162* dst = (__nv_bfloat162*)(g_xn + (size_t)t * HDIM);
    dst[tid * 2 + 0] = __floats2bfloat162_rn(xn4.x, xn4.y);
    dst[tid * 2 + 1] = __floats2bfloat162_rn(xn4.z, xn4.w);
    __syncthreads();

    // router logits in fp32: thread (e = tid&15, hl = tid>>4)
    int e  = tid & 15;
    int hl = tid >> 4;
    float acc = 0.f;
    #pragma unroll 8
    for (int j = 0; j < 64; j++) {
        int h = hl + j * 16;
        acc += xs[h] * wg[h * NEXP + e];
    }
    red[tid] = acc;
    __syncthreads();
    if (tid < 128) red[tid] += red[tid + 128];
    __syncthreads();
    if (tid < 64) red[tid] += red[tid + 64];
    __syncthreads();
    if (tid < 32) red[tid] += red[tid + 32];
    __syncthreads();
    if (tid < 16) l16[tid] = red[tid] + red[tid + 16] + bg[tid];
    __syncthreads();

    if (tid == 0) {
        float vals[TOPK];
        int   ids[TOPK];
        unsigned mask = 0;
        #pragma unroll
        for (int k = 0; k < TOPK; k++) {
            float best = -1e30f; int bi = 0;
            #pragma unroll
            for (int e2 = 0; e2 < NEXP; e2++) {
                if (!((mask >> e2) & 1u) && l16[e2] > best) { best = l16[e2]; bi = e2; }
            }
            mask |= 1u << bi; vals[k] = best; ids[k] = bi;
        }
        float m = vals[0], sum = 0.f, g[TOPK];
        #pragma unroll
        for (int k = 0; k < TOPK; k++) { g[k] = expf(vals[k] - m); sum += g[k]; }
        float inv = 1.0f / sum;
        #pragma unroll
        for (int k = 0; k < TOPK; k++) {
            int ee  = ids[k];
            int pos = atomicAdd(&g_cnt[ee], 1);
            int slot = ee * T_TOK + pos;
            g_tok[slot]  = t;
            g_gate[slot] = g[k] * inv;
            g_slot_of[t * TOPK + k] = slot;
        }
    }
}

// ---------------- grouped GEMM tiles ----------------
#define BM 128
#define BN 64
#define BK 32
#define AS_STR (BK + 8)   // 40 bf16 (80B rows; 16B-multiple, conflict-free ldmatrix)
#define BS_STR (BN + 8)   // 72 bf16 (144B rows)

// ---------------- kernel 2: FFN1 grouped GEMM + SwiGLU ----------------
__global__ void __launch_bounds__(256) ffn1_kernel(const float* __restrict__ w1,
                                                   const float* __restrict__ b1) {
    int e = blockIdx.z;
    int cnt = g_cnt[e];
    int row0 = blockIdx.y * BM;
    if (row0 >= cnt) return;
    int n0 = blockIdx.x * BN;

    __shared__ __align__(16) __nv_bfloat16 As[BM * AS_STR];
    __shared__ __align__(16) __nv_bfloat16 Bs[BK * BS_STR];
    __shared__ int toks[BM];

    int tid = threadIdx.x;
    if (tid < BM) toks[tid] = g_tok[e * T_TOK + min(row0 + tid, cnt - 1)];
    __syncthreads();

    int warp = tid >> 5, lane = tid & 31;
    int mw = (warp >> 1) * 32;
    int nw = (warp & 1) * 32;
    float c[2][4][4];
    #pragma unroll
    for (int i = 0; i < 2; i++)
        #pragma unroll
        for (int j = 0; j < 4; j++)
            #pragma unroll
            for (int q = 0; q < 4; q++) c[i][j][q] = 0.f;

    const float* wbase = w1 + (size_t)e * HDIM * (2 * IDIM) + n0;

    for (int k0 = 0; k0 < HDIM; k0 += BK) {
        // A tile: 128 x 32 bf16 gathered rows, 8B per thread x4
        #pragma unroll
        for (int j = 0; j < 4; j++) {
            int s = tid + j * 256;
            int rr = s >> 3, cc = (s & 7) << 2;
            *(uint2*)&As[rr * AS_STR + cc] =
                *(const uint2*)(g_xn + ((size_t)toks[rr] << 10) + k0 + cc);
        }
        // B tile: 32 x 64 fp32 -> bf16
        #pragma unroll
        for (int j = 0; j < 2; j++) {
            int s = tid + j * 256;
            int kr = s >> 4, c4 = (s & 15) << 2;
            float4 v = *(const float4*)(wbase + (size_t)(k0 + kr) * (2 * IDIM) + c4);
            __nv_bfloat162 p0 = __floats2bfloat162_rn(v.x, v.y);
            __nv_bfloat162 p1 = __floats2bfloat162_rn(v.z, v.w);
            uint2 u;
            u.x = *(uint32_t*)&p0; u.y = *(uint32_t*)&p1;
            *(uint2*)&Bs[kr * BS_STR + c4] = u;
        }
        __syncthreads();
        #pragma unroll
        for (int ks = 0; ks < 2; ks++) {
            int kk = ks * 16;
            uint32_t a[2][4], b[4][2];
            #pragma unroll
            for (int mt = 0; mt < 2; mt++) {
                int rowm = mw + mt * 16 + (lane & 15);
                int colk = kk + ((lane >> 4) << 3);
                ldsm_x4(a[mt][0], a[mt][1], a[mt][2], a[mt][3],
                        smem_u32(&As[rowm * AS_STR + colk]));
            }
            #pragma unroll
            for (int nt = 0; nt < 4; nt++) {
                int krow = kk + (lane & 15);
                ldsm_x2_t(b[nt][0], b[nt][1],
                          smem_u32(&Bs[krow * BS_STR + nw + nt * 8]));
            }
            #pragma unroll
            for (int mt = 0; mt < 2; mt++)
                #pragma unroll
                for (int nt = 0; nt < 4; nt++)
                    mma_bf16(c[mt][nt], a[mt][0], a[mt][1], a[mt][2], a[mt][3],
                             b[nt][0], b[nt][1]);
        }
        __syncthreads();
    }

    // epilogue: bias + interleaved SwiGLU -> s (bf16)
    int lr = lane >> 2, lc2 = lane & 3;
    const float* b1e = b1 + e * (2 * IDIM);
    #pragma unroll
    for (int mt = 0; mt < 2; mt++) {
        #pragma unroll
        for (int nt = 0; nt < 4; nt++) {
            int ncol = n0 + nw + nt * 8 + lc2 * 2;
            float bb0 = b1e[ncol], bb1 = b1e[ncol + 1];
            int scol = ((n0 + nw) >> 1) + nt * 4 + lc2;
            int rl = mw + mt * 16 + lr;
            if (row0 + rl < cnt) {
                float s = swiglu(c[mt][nt][0] + bb0, c[mt][nt][1] + bb1);
                g_s[(size_t)(e * T_TOK + row0 + rl) * IDIM + scol] = __float2bfloat16(s);
            }
            if (row0 + rl + 8 < cnt) {
                float s = swiglu(c[mt][nt][2] + bb0, c[mt][nt][3] + bb1);
                g_s[(size_t)(e * T_TOK + row0 + rl + 8) * IDIM + scol] = __float2bfloat16(s);
            }
        }
    }
}

// ---------------- kernel 3: FFN2 grouped GEMM + bias + gate ----------------
__global__ void __launch_bounds__(256) ffn2_kernel(const float* __restrict__ w2,
                                                   const float* __restrict__ b2) {
    int e = blockIdx.z;
    int cnt = g_cnt[e];
    int row0 = blockIdx.y * BM;
    if (row0 >= cnt) return;
    int n0 = blockIdx.x * BN;

    __shared__ __align__(16) __nv_bfloat16 As[BM * AS_STR];
    __shared__ __align__(16) __nv_bfloat16 Bs[BK * BS_STR];

    int tid = threadIdx.x;
    int warp = tid >> 5, lane = tid & 31;
    int mw = (warp >> 1) * 32;
    int nw = (warp & 1) * 32;
    float c[2][4][4];
    #pragma unroll
    for (int i = 0; i < 2; i++)
        #pragma unroll
        for (int j = 0; j < 4; j++)
            #pragma unroll
            for (int q = 0; q < 4; q++) c[i][j][q] = 0.f;

    const float* wbase = w2 + (size_t)e * IDIM * HDIM + n0;
    const __nv_bfloat16* sbase = g_s + (size_t)e * T_TOK * IDIM;

    for (int k0 = 0; k0 < IDIM; k0 += BK) {
        #pragma unroll
        for (int j = 0; j < 4; j++) {
            int s = tid + j * 256;
            int rr = s >> 3, cc = (s & 7) << 2;
            int rowg = min(row0 + rr, cnt - 1);
            *(uint2*)&As[rr * AS_STR + cc] =
                *(const uint2*)(sbase + ((size_t)rowg << 10) + k0 + cc);
        }
        #pragma unroll
        for (int j = 0; j < 2; j++) {
            int s = tid + j * 256;
            int kr = s >> 4, c4 = (s & 15) << 2;
            float4 v = *(const float4*)(wbase + (size_t)(k0 + kr) * HDIM + c4);
            __nv_bfloat162 p0 = __floats2bfloat162_rn(v.x, v.y);
            __nv_bfloat162 p1 = __floats2bfloat162_rn(v.z, v.w);
            uint2 u;
            u.x = *(uint32_t*)&p0; u.y = *(uint32_t*)&p1;
            *(uint2*)&Bs[kr * BS_STR + c4] = u;
        }
        __syncthreads();
        #pragma unroll
        for (int ks = 0; ks < 2; ks++) {
            int kk = ks * 16;
            uint32_t a[2][4], b[4][2];
            #pragma unroll
            for (int mt = 0; mt < 2; mt++) {
                int rowm = mw + mt * 16 + (lane & 15);
                int colk = kk + ((lane >> 4) << 3);
                ldsm_x4(a[mt][0], a[mt][1], a[mt][2], a[mt][3],
                        smem_u32(&As[rowm * AS_STR + colk]));
            }
            #pragma unroll
            for (int nt = 0; nt < 4; nt++) {
                int krow = kk + (lane & 15);
                ldsm_x2_t(b[nt][0], b[nt][1],
                          smem_u32(&Bs[krow * BS_STR + nw + nt * 8]));
            }
            #pragma unroll
            for (int mt = 0; mt < 2; mt++)
                #pragma unroll
                for (int nt = 0; nt < 4; nt++)
                    mma_bf16(c[mt][nt], a[mt][0], a[mt][1], a[mt][2], a[mt][3],
                             b[nt][0], b[nt][1]);
        }
        __syncthreads();
    }

    // epilogue: bias + gate scale -> y (fp32)
    int lr = lane >> 2, lc2 = lane & 3;
    const float* b2e = b2 + e * HDIM;
    #pragma unroll
    for (int mt = 0; mt < 2; mt++) {
        int rl = mw + mt * 16 + lr;
        #pragma unroll
        for (int nt = 0; nt < 4; nt++) {
            int ncol = n0 + nw + nt * 8 + lc2 * 2;
            float bb0 = b2e[ncol], bb1 = b2e[ncol + 1];
            if (row0 + rl < cnt) {
                float gate = g_gate[e * T_TOK + row0 + rl];
                float2 yv = make_float2((c[mt][nt][0] + bb0) * gate,
                                        (c[mt][nt][1] + bb1) * gate);
                *(float2*)&g_y[(size_t)(e * T_TOK + row0 + rl) * HDIM + ncol] = yv;
            }
            if (row0 + rl + 8 < cnt) {
                float gate = g_gate[e * T_TOK + row0 + rl + 8];
                float2 yv = make_float2((c[mt][nt][2] + bb0) * gate,
                                        (c[mt][nt][3] + bb1) * gate);
                *(float2*)&g_y[(size_t)(e * T_TOK + row0 + rl + 8) * HDIM + ncol] = yv;
            }
        }
    }
}

// ---------------- kernel 4: combine out = x + sum_k y[slot(t,k)] ----------------
__global__ void __launch_bounds__(256) combine_kernel(const float* __restrict__ x,
                                                      float* __restrict__ out) {
    int t = blockIdx.x;
    int tid = threadIdx.x;
    int s0 = g_slot_of[t * TOPK + 0];
    int s1 = g_slot_of[t * TOPK + 1];
    int s2 = g_slot_of[t * TOPK + 2];
    int s3 = g_slot_of[t * TOPK + 3];
    size_t off = (size_t)tid * 4;
    float4 a = *(const float4*)(x + (size_t)t * HDIM + off);
    float4 y0 = *(const float4*)(g_y + (size_t)s0 * HDIM + off);
    float4 y1 = *(const float4*)(g_y + (size_t)s1 * HDIM + off);
    float4 y2 = *(const float4*)(g_y + (size_t)s2 * HDIM + off);
    float4 y3 = *(const float4*)(g_y + (size_t)s3 * HDIM + off);
    a.x += y0.x + y1.x + y2.x + y3.x;
    a.y += y0.y + y1.y + y2.y + y3.y;
    a.z += y0.z + y1.z + y2.z + y3.z;
    a.w += y0.w + y1.w + y2.w + y3.w;
    *(float4*)(out + (size_t)t * HDIM + off) = a;
}

// ---------------- launch ----------------
extern "C" void kernel_launch(void* const* d_in, const int* in_sizes, int n_in,
                              void* d_out, int out_size) {
    const float* x      = (const float*)d_in[0];
    const float* nscale = (const float*)d_in[1];
    const float* wg     = (const float*)d_in[2];
    const float* bg     = (const float*)d_in[3];
    const float* w1     = (const float*)d_in[4];
    const float* b1     = (const float*)d_in[5];
    const float* w2     = (const float*)d_in[6];
    const float* b2     = (const float*)d_in[7];
    float* out = (float*)d_out;

    zero_cnt_kernel<<<1, 32>>>();
    rms_router_kernel<<<T_TOK, 256>>>(x, nscale, wg, bg);
    ffn1_kernel<<<dim3((2 * IDIM) / BN, T_TOK / BM, NEXP), 256>>>(w1, b1);
    ffn2_kernel<<<dim3(HDIM / BN, T_TOK / BM, NEXP), 256>>>(w2, b2);
    combine_kernel<<<T_TOK, 256>>>(x, out);
}

// round 2
// speedup vs baseline: 1.4631x; 1.4631x over previous
#include <cuda_runtime.h>
#include <cuda_bf16.h>
#include <cstdint>

// ---------------- problem constants ----------------
#define T_TOK 1024
#define HDIM  1024
#define IDIM  1024
#define NEXP  16
#define TOPK  4
#define LIMIT 7.0f
#define ALPHA 1.702f
#define EPS   1e-5f

// ---------------- scratch ----------------
__device__ __nv_bfloat16 g_xn[(size_t)T_TOK * HDIM];
__device__ __nv_bfloat16 g_s[(size_t)NEXP * T_TOK * IDIM];
__device__ float         g_y[(size_t)NEXP * T_TOK * HDIM];
__device__ int           g_tok[NEXP * T_TOK];
__device__ float         g_gate[NEXP * T_TOK];
__device__ int           g_slot_of[T_TOK * TOPK];
__device__ int           g_cnt[NEXP];

// ---------------- helpers ----------------
__device__ __forceinline__ uint32_t smem_u32(const void* p) {
    return (uint32_t)__cvta_generic_to_shared(p);
}
__device__ __forceinline__ void cp16(void* s, const void* g) {
    asm volatile("cp.async.ca.shared.global [%0],[%1],16;\n" :: "r"(smem_u32(s)), "l"(g));
}
__device__ __forceinline__ void cp_commit() { asm volatile("cp.async.commit_group;\n"); }
__device__ __forceinline__ void cp_wait0()  { asm volatile("cp.async.wait_group 0;\n"); }

__device__ __forceinline__ void ldsm_x4(uint32_t& r0, uint32_t& r1, uint32_t& r2, uint32_t& r3, uint32_t a) {
    asm volatile("ldmatrix.sync.aligned.m8n8.x4.shared.b16 {%0,%1,%2,%3},[%4];\n"
                 : "=r"(r0), "=r"(r1), "=r"(r2), "=r"(r3) : "r"(a));
}
__device__ __forceinline__ void ldsm_x4_t(uint32_t& r0, uint32_t& r1, uint32_t& r2, uint32_t& r3, uint32_t a) {
    asm volatile("ldmatrix.sync.aligned.m8n8.x4.trans.shared.b16 {%0,%1,%2,%3},[%4];\n"
                 : "=r"(r0), "=r"(r1), "=r"(r2), "=r"(r3) : "r"(a));
}
__device__ __forceinline__ void mma_bf16(float c[4],
                                         uint32_t a0, uint32_t a1, uint32_t a2, uint32_t a3,
                                         uint32_t b0, uint32_t b1) {
    asm volatile("mma.sync.aligned.m16n8k16.row.col.f32.bf16.bf16.f32 "
                 "{%0,%1,%2,%3},{%4,%5,%6,%7},{%8,%9},{%0,%1,%2,%3};\n"
                 : "+f"(c[0]), "+f"(c[1]), "+f"(c[2]), "+f"(c[3])
                 : "r"(a0), "r"(a1), "r"(a2), "r"(a3), "r"(b0), "r"(b1));
}
__device__ __forceinline__ float swiglu(float hg, float hl) {
    float a  = fminf(hg, LIMIT);
    float bb = fminf(fmaxf(hl, -LIMIT), LIMIT);
    return a * (1.0f / (1.0f + expf(-ALPHA * a))) * (bb + 1.0f);
}

// ---------------- kernel 0 ----------------
__global__ void zero_cnt_kernel() {
    if (threadIdx.x < NEXP) g_cnt[threadIdx.x] = 0;
}

// ---------------- kernel 1: RMSNorm + fp32 router + top-4 + scatter ----------------
__global__ void __launch_bounds__(256) rms_router_kernel(
    const float* __restrict__ x, const float* __restrict__ nscale,
    const float* __restrict__ wg, const float* __restrict__ bg) {
    int t   = blockIdx.x;
    int tid = threadIdx.x;
    __shared__ float xs[HDIM];
    __shared__ float red[256];
    __shared__ float l16[NEXP];

    float4 v = ((const float4*)(x + (size_t)t * HDIM))[tid];
    float ss = v.x * v.x + v.y * v.y + v.z * v.z + v.w * v.w;
    #pragma unroll
    for (int o = 16; o; o >>= 1) ss += __shfl_xor_sync(0xFFFFFFFFu, ss, o);
    if ((tid & 31) == 0) red[tid >> 5] = ss;
    __syncthreads();
    if (tid == 0) {
        float s = 0.f;
        #pragma unroll
        for (int i = 0; i < 8; i++) s += red[i];
        red[0] = rsqrtf(s * (1.0f / HDIM) + EPS);
    }
    __syncthreads();
    float r = red[0];
    float4 sc = ((const float4*)nscale)[tid];
    float4 xn4 = make_float4(v.x * r * sc.x, v.y * r * sc.y, v.z * r * sc.z, v.w * r * sc.w);
    xs[tid * 4 + 0] = xn4.x; xs[tid * 4 + 1] = xn4.y;
    xs[tid * 4 + 2] = xn4.z; xs[tid * 4 + 3] = xn4.w;
    __nv_bfloat162* dst = (__nv_bfloat162*)(g_xn + (size_t)t * HDIM);
    dst[tid * 2 + 0] = __floats2bfloat162_rn(xn4.x, xn4.y);
    dst[tid * 2 + 1] = __floats2bfloat162_rn(xn4.z, xn4.w);
    __syncthreads();

    int e  = tid & 15;
    int hl = tid >> 4;
    float acc = 0.f;
    #pragma unroll 8
    for (int j = 0; j < 64; j++) {
        int h = hl + j * 16;
        acc += xs[h] * wg[h * NEXP + e];
    }
    red[tid] = acc;
    __syncthreads();
    if (tid < 128) red[tid] += red[tid + 128];
    __syncthreads();
    if (tid < 64) red[tid] += red[tid + 64];
    __syncthreads();
    if (tid < 32) red[tid] += red[tid + 32];
    __syncthreads();
    if (tid < 16) l16[tid] = red[tid] + red[tid + 16] + bg[tid];
    __syncthreads();

    if (tid == 0) {
        float vals[TOPK];
        int   ids[TOPK];
        unsigned mask = 0;
        #pragma unroll
        for (int k = 0; k < TOPK; k++) {
            float best = -1e30f; int bi = 0;
            #pragma unroll
            for (int e2 = 0; e2 < NEXP; e2++) {
                if (!((mask >> e2) & 1u) && l16[e2] > best) { best = l16[e2]; bi = e2; }
            }
            mask |= 1u << bi; vals[k] = best; ids[k] = bi;
        }
        float m = vals[0], sum = 0.f, g[TOPK];
        #pragma unroll
        for (int k = 0; k < TOPK; k++) { g[k] = expf(vals[k] - m); sum += g[k]; }
        float inv = 1.0f / sum;
        #pragma unroll
        for (int k = 0; k < TOPK; k++) {
            int ee  = ids[k];
            int pos = atomicAdd(&g_cnt[ee], 1);
            int slot = ee * T_TOK + pos;
            g_tok[slot]  = t;
            g_gate[slot] = g[k] * inv;
            g_slot_of[t * TOPK + k] = slot;
        }
    }
}

// ---------------- grouped GEMM config ----------------
#define BM 128
#define BN 128
#define BK 32
#define AS_STR (BK + 8)    // 40 bf16 = 80B rows (odd multiple of 16B -> conflict-free)
#define BS_STR (BN + 8)    // 136 bf16 = 272B rows (17*16B -> conflict-free)
#define NIT (HDIM / BK)    // 32

// A tile cp.async: 128 rows x 64B, 512 chunks of 16B, 2 per thread.
// B tile: 32 rows x BN fp32; each thread: 1 row, 16 consecutive floats.

struct BPrefetch { float4 f[4]; };

__device__ __forceinline__ void loadB_regs(BPrefetch& p, const float* wrow, int c16) {
    #pragma unroll
    for (int j = 0; j < 4; j++) p.f[j] = *(const float4*)(wrow + c16 + j * 4);
}
__device__ __forceinline__ void storeB_smem(__nv_bfloat16* Bs, const BPrefetch& p, int kr, int c16) {
    uint32_t u[8];
    #pragma unroll
    for (int j = 0; j < 4; j++) {
        __nv_bfloat162 p0 = __floats2bfloat162_rn(p.f[j].x, p.f[j].y);
        __nv_bfloat162 p1 = __floats2bfloat162_rn(p.f[j].z, p.f[j].w);
        u[j * 2 + 0] = *(uint32_t*)&p0;
        u[j * 2 + 1] = *(uint32_t*)&p1;
    }
    uint4* d = (uint4*)&Bs[kr * BS_STR + c16];
    d[0] = make_uint4(u[0], u[1], u[2], u[3]);
    d[1] = make_uint4(u[4], u[5], u[6], u[7]);
}

// compute one BK tile: 2 ksteps, warp tile 32(m) x 64(n)
__device__ __forceinline__ void mma_tile(float c[2][8][4],
                                         const __nv_bfloat16* As, const __nv_bfloat16* Bs,
                                         int mw, int nw, int lane) {
    #pragma unroll
    for (int ks = 0; ks < 2; ks++) {
        int kk = ks * 16;
        uint32_t a[2][4], b[8][2];
        #pragma unroll
        for (int mt = 0; mt < 2; mt++) {
            int rowm = mw + mt * 16 + (lane & 15);
            int colk = kk + ((lane >> 4) << 3);
            ldsm_x4(a[mt][0], a[mt][1], a[mt][2], a[mt][3],
                    smem_u32(&As[rowm * AS_STR + colk]));
        }
        #pragma unroll
        for (int np = 0; np < 4; np++) {
            int krow = kk + (lane & 15);
            int ncol = nw + np * 16 + ((lane >> 4) << 3);
            ldsm_x4_t(b[np * 2][0], b[np * 2][1], b[np * 2 + 1][0], b[np * 2 + 1][1],
                      smem_u32(&Bs[krow * BS_STR + ncol]));
        }
        #pragma unroll
        for (int mt = 0; mt < 2; mt++)
            #pragma unroll
            for (int nt = 0; nt < 8; nt++)
                mma_bf16(c[mt][nt], a[mt][0], a[mt][1], a[mt][2], a[mt][3],
                         b[nt][0], b[nt][1]);
    }
}

// ---------------- kernel 2: FFN1 grouped GEMM + SwiGLU ----------------
__global__ void __launch_bounds__(256, 2) ffn1_kernel(const float* __restrict__ w1,
                                                      const float* __restrict__ b1) {
    int e = blockIdx.z;
    int cnt = g_cnt[e];
    int row0 = blockIdx.y * BM;
    if (row0 >= cnt) return;
    int n0 = blockIdx.x * BN;

    __shared__ __align__(16) __nv_bfloat16 As[2][BM * AS_STR];
    __shared__ __align__(16) __nv_bfloat16 Bs[2][BK * BS_STR];
    __shared__ int toks[BM];

    int tid = threadIdx.x;
    if (tid < BM) toks[tid] = g_tok[e * T_TOK + min(row0 + tid, cnt - 1)];
    __syncthreads();

    int warp = tid >> 5, lane = tid & 31;
    int mw = (warp >> 1) * 32;
    int nw = (warp & 1) * 64;
    float c[2][8][4];
    #pragma unroll
    for (int i = 0; i < 2; i++)
        #pragma unroll
        for (int j = 0; j < 8; j++)
            #pragma unroll
            for (int q = 0; q < 4; q++) c[i][j][q] = 0.f;

    const float* wbase = w1 + (size_t)e * HDIM * (2 * IDIM) + n0;
    const int ldw = 2 * IDIM;

    // A chunk coords (2 chunks per thread)
    int ar0 = tid >> 2,            ac0 = (tid & 3) * 8;
    int ar1 = (tid + 256) >> 2,    ac1 = ((tid + 256) & 3) * 8;
    // B coords: 1 row, 16 floats per thread
    int bkr = tid >> 3, bc16 = (tid & 7) * 16;

    // prologue: tile 0
    cp16(&As[0][ar0 * AS_STR + ac0], g_xn + ((size_t)toks[ar0] << 10) + ac0);
    cp16(&As[0][ar1 * AS_STR + ac1], g_xn + ((size_t)toks[ar1] << 10) + ac1);
    cp_commit();
    BPrefetch bp;
    loadB_regs(bp, wbase + (size_t)bkr * ldw, bc16);
    storeB_smem(Bs[0], bp, bkr, bc16);
    cp_wait0();
    __syncthreads();

    for (int it = 0; it < NIT; it++) {
        int cur = it & 1, nxt = cur ^ 1;
        int k1 = (it + 1) * BK;
        if (it + 1 < NIT) {
            cp16(&As[nxt][ar0 * AS_STR + ac0], g_xn + ((size_t)toks[ar0] << 10) + k1 + ac0);
            cp16(&As[nxt][ar1 * AS_STR + ac1], g_xn + ((size_t)toks[ar1] << 10) + k1 + ac1);
            cp_commit();
            loadB_regs(bp, wbase + (size_t)(k1 + bkr) * ldw, bc16);
        }
        mma_tile(c, As[cur], Bs[cur], mw, nw, lane);
        if (it + 1 < NIT) storeB_smem(Bs[nxt], bp, bkr, bc16);
        cp_wait0();
        __syncthreads();
    }

    // epilogue: bias + interleaved SwiGLU -> g_s (bf16)
    int lr = lane >> 2, lc2 = lane & 3;
    const float* b1e = b1 + e * (2 * IDIM);
    #pragma unroll
    for (int mt = 0; mt < 2; mt++) {
        #pragma unroll
        for (int nt = 0; nt < 8; nt++) {
            int ncol = n0 + nw + nt * 8 + lc2 * 2;
            float bb0 = b1e[ncol], bb1 = b1e[ncol + 1];
            int scol = ((n0 + nw) >> 1) + nt * 4 + lc2;
            int rl = mw + mt * 16 + lr;
            if (row0 + rl < cnt) {
                float s = swiglu(c[mt][nt][0] + bb0, c[mt][nt][1] + bb1);
                g_s[(size_t)(e * T_TOK + row0 + rl) * IDIM + scol] = __float2bfloat16(s);
            }
            if (row0 + rl + 8 < cnt) {
                float s = swiglu(c[mt][nt][2] + bb0, c[mt][nt][3] + bb1);
                g_s[(size_t)(e * T_TOK + row0 + rl + 8) * IDIM + scol] = __float2bfloat16(s);
            }
        }
    }
}

// ---------------- kernel 3: FFN2 grouped GEMM + bias + gate ----------------
__global__ void __launch_bounds__(256, 2) ffn2_kernel(const float* __restrict__ w2,
                                                      const float* __restrict__ b2) {
    int e = blockIdx.z;
    int cnt = g_cnt[e];
    int row0 = blockIdx.y * BM;
    if (row0 >= cnt) return;
    int n0 = blockIdx.x * BN;

    __shared__ __align__(16) __nv_bfloat16 As[2][BM * AS_STR];
    __shared__ __align__(16) __nv_bfloat16 Bs[2][BK * BS_STR];

    int tid = threadIdx.x;
    int warp = tid >> 5, lane = tid & 31;
    int mw = (warp >> 1) * 32;
    int nw = (warp & 1) * 64;
    float c[2][8][4];
    #pragma unroll
    for (int i = 0; i < 2; i++)
        #pragma unroll
        for (int j = 0; j < 8; j++)
            #pragma unroll
            for (int q = 0; q < 4; q++) c[i][j][q] = 0.f;

    const float* wbase = w2 + (size_t)e * IDIM * HDIM + n0;
    const int ldw = HDIM;
    const __nv_bfloat16* sbase = g_s + (size_t)e * T_TOK * IDIM;

    int ar0 = tid >> 2,         ac0 = (tid & 3) * 8;
    int ar1 = (tid + 256) >> 2, ac1 = ((tid + 256) & 3) * 8;
    size_t srow0 = (size_t)min(row0 + ar0, cnt - 1) << 10;
    size_t srow1 = (size_t)min(row0 + ar1, cnt - 1) << 10;
    int bkr = tid >> 3, bc16 = (tid & 7) * 16;

    cp16(&As[0][ar0 * AS_STR + ac0], sbase + srow0 + ac0);
    cp16(&As[0][ar1 * AS_STR + ac1], sbase + srow1 + ac1);
    cp_commit();
    BPrefetch bp;
    loadB_regs(bp, wbase + (size_t)bkr * ldw, bc16);
    storeB_smem(Bs[0], bp, bkr, bc16);
    cp_wait0();
    __syncthreads();

    for (int it = 0; it < NIT; it++) {
        int cur = it & 1, nxt = cur ^ 1;
        int k1 = (it + 1) * BK;
        if (it + 1 < NIT) {
            cp16(&As[nxt][ar0 * AS_STR + ac0], sbase + srow0 + k1 + ac0);
            cp16(&As[nxt][ar1 * AS_STR + ac1], sbase + srow1 + k1 + ac1);
            cp_commit();
            loadB_regs(bp, wbase + (size_t)(k1 + bkr) * ldw, bc16);
        }
        mma_tile(c, As[cur], Bs[cur], mw, nw, lane);
        if (it + 1 < NIT) storeB_smem(Bs[nxt], bp, bkr, bc16);
        cp_wait0();
        __syncthreads();
    }

    int lr = lane >> 2, lc2 = lane & 3;
    const float* b2e = b2 + e * HDIM;
    #pragma unroll
    for (int mt = 0; mt < 2; mt++) {
        int rl = mw + mt * 16 + lr;
        #pragma unroll
        for (int nt = 0; nt < 8; nt++) {
            int ncol = n0 + nw + nt * 8 + lc2 * 2;
            float bb0 = b2e[ncol], bb1 = b2e[ncol + 1];
            if (row0 + rl < cnt) {
                float gate = g_gate[e * T_TOK + row0 + rl];
                float2 yv = make_float2((c[mt][nt][0] + bb0) * gate,
                                        (c[mt][nt][1] + bb1) * gate);
                *(float2*)&g_y[(size_t)(e * T_TOK + row0 + rl) * HDIM + ncol] = yv;
            }
            if (row0 + rl + 8 < cnt) {
                float gate = g_gate[e * T_TOK + row0 + rl + 8];
                float2 yv = make_float2((c[mt][nt][2] + bb0) * gate,
                                        (c[mt][nt][3] + bb1) * gate);
                *(float2*)&g_y[(size_t)(e * T_TOK + row0 + rl + 8) * HDIM + ncol] = yv;
            }
        }
    }
}

// ---------------- kernel 4: combine ----------------
__global__ void __launch_bounds__(256) combine_kernel(const float* __restrict__ x,
                                                      float* __restrict__ out) {
    int t = blockIdx.x;
    int tid = threadIdx.x;
    int s0 = g_slot_of[t * TOPK + 0];
    int s1 = g_slot_of[t * TOPK + 1];
    int s2 = g_slot_of[t * TOPK + 2];
    int s3 = g_slot_of[t * TOPK + 3];
    size_t off = (size_t)tid * 4;
    float4 a = *(const float4*)(x + (size_t)t * HDIM + off);
    float4 y0 = *(const float4*)(g_y + (size_t)s0 * HDIM + off);
    float4 y1 = *(const float4*)(g_y + (size_t)s1 * HDIM + off);
    float4 y2 = *(const float4*)(g_y + (size_t)s2 * HDIM + off);
    float4 y3 = *(const float4*)(g_y + (size_t)s3 * HDIM + off);
    a.x += y0.x + y1.x + y2.x + y3.x;
    a.y += y0.y + y1.y + y2.y + y3.y;
    a.z += y0.z + y1.z + y2.z + y3.z;
    a.w += y0.w + y1.w + y2.w + y3.w;
    *(float4*)(out + (size_t)t * HDIM + off) = a;
}

// ---------------- launch ----------------
extern "C" void kernel_launch(void* const* d_in, const int* in_sizes, int n_in,
                              void* d_out, int out_size) {
    const float* x      = (const float*)d_in[0];
    const float* nscale = (const float*)d_in[1];
    const float* wg     = (const float*)d_in[2];
    const float* bg     = (const float*)d_in[3];
    const float* w1     = (const float*)d_in[4];
    const float* b1     = (const float*)d_in[5];
    const float* w2     = (const float*)d_in[6];
    const float* b2     = (const float*)d_in[7];
    float* out = (float*)d_out;

    zero_cnt_kernel<<<1, 32>>>();
    rms_router_kernel<<<T_TOK, 256>>>(x, nscale, wg, bg);
    ffn1_kernel<<<dim3((2 * IDIM) / BN, T_TOK / BM, NEXP), 256>>>(w1, b1);
    ffn2_kernel<<<dim3(HDIM / BN, T_TOK / BM, NEXP), 256>>>(w2, b2);
    combine_kernel<<<T_TOK, 256>>>(x, out);
}